// round 10
// baseline (speedup 1.0000x reference)
#include <cuda_runtime.h>
#include <cuda_fp16.h>
#include <cstdint>

#define SEQ 4096
#define EMB 1024

// ---------------- scratch (static, allocation-free) ----------------
__device__ __half g_Xh [(size_t)SEQ * EMB];
__device__ __half g_Wqt[(size_t)EMB * EMB];
__device__ __half g_Wkt[(size_t)EMB * EMB];
__device__ __half g_Wvt[(size_t)EMB * EMB];
__device__ __half g_Qh [(size_t)SEQ * EMB];
__device__ __half g_Kh [(size_t)SEQ * EMB];
__device__ __half g_Vh [(size_t)SEQ * EMB];
__device__ __half g_Vt [(size_t)EMB * SEQ];
__device__ __half g_Sh [(size_t)SEQ * SEQ];
__device__ float  g_part[(size_t)SEQ * 64];   // per (row, colCTA*4+wn) partials

// ---------------- helpers ----------------
__device__ __forceinline__ uint32_t smem_u32(const void* p) {
    return (uint32_t)__cvta_generic_to_shared(p);
}
__device__ __forceinline__ void cp16(uint32_t s, const void* g) {
    asm volatile("cp.async.cg.shared.global [%0], [%1], 16;" :: "r"(s), "l"(g));
}
__device__ __forceinline__ void cp_commit() {
    asm volatile("cp.async.commit_group;" ::: "memory");
}
template <int N>
__device__ __forceinline__ void cp_wait() {
    asm volatile("cp.async.wait_group %0;" :: "n"(N) : "memory");
}
__device__ __forceinline__ float ex2_mufu(float y) {
    float r;
    asm("ex2.approx.ftz.f32 %0, %1;" : "=f"(r) : "f"(y));
    return r;
}
// exact-split exp2 on the FMA pipe (y = n + f, f in [-.5,.5], degree-5 poly)
__device__ __forceinline__ float ex2_fma(float y) {
    const float MAGIC = 12582912.0f;          // 1.5 * 2^23
    float tm = __fadd_rn(y, MAGIC);
    float f  = __fadd_rn(y, -__fadd_rn(tm, -MAGIC));
    int   eb = (__float_as_int(tm) << 23) + 0x3F800000;
    float pl = 0.0013333558f;
    pl = fmaf(pl, f, 0.0096181291f);
    pl = fmaf(pl, f, 0.0555041087f);
    pl = fmaf(pl, f, 0.2402265069f);
    pl = fmaf(pl, f, 0.6931471806f);
    pl = fmaf(pl, f, 1.0f);
    return __int_as_float(eb) * pl;
}
// m16n8k16 fp16 MMA, fp32 accumulate
__device__ __forceinline__ void mma_f16(
    float& c0, float& c1, float& c2, float& c3,
    uint32_t a0, uint32_t a1, uint32_t a2, uint32_t a3,
    uint32_t b0, uint32_t b1)
{
    asm volatile(
        "mma.sync.aligned.m16n8k16.row.col.f32.f16.f16.f32 "
        "{%0,%1,%2,%3}, {%4,%5,%6,%7}, {%8,%9}, {%0,%1,%2,%3};"
        : "+f"(c0), "+f"(c1), "+f"(c2), "+f"(c3)
        : "r"(a0), "r"(a1), "r"(a2), "r"(a3), "r"(b0), "r"(b1));
}

// ---------------------------------------------------------------------------
// FP16 tensor-core NT GEMM: C[M,N] = f( A[M,K] @ B[N,K]^T )
// CTA tile 128x256, 256 threads (8 warps 2x4), warp tile 64x64, BK=64,
// 3-stage cp.async, one __syncthreads/iter, XOR-swizzled smem,
// scalar-LDS fragment loads (known-good warp-level mainloop).
// MODE 0: fp16 out (projections)
// MODE 1: Sh = fp16(exp(alpha*acc)); per-(row,warp) partial sums -> part
// MODE 2: fp32 out scaled by rsum computed in prologue from part
// ---------------------------------------------------------------------------
#define STG 3
#define OPWA (128 * 32)                // A-tile fp16x2 words (16KB)
#define OPWB (256 * 32)                // B-tile fp16x2 words (32KB)
#define STW  (OPWA + OPWB)             // words per stage (48KB)
#define GEMM_DYNSMEM (STG * STW * 4)   // 147456 bytes

template <int MODE>
__device__ __forceinline__ void gemm_body(
    const __half* __restrict__ A, const __half* __restrict__ B,
    void* __restrict__ Cv, int N, int K, float alpha,
    float* __restrict__ part, int bm, int bn, int bx)
{
    extern __shared__ uint32_t sm[];
    __shared__ float rsm[128];

    const int tid  = threadIdx.x;
    const int warp = tid >> 5;
    const int lane = tid & 31;
    const int g    = lane >> 2;
    const int t    = lane & 3;
    const int wm   = warp & 1;      // 2 x 64 rows
    const int wn   = warp >> 1;     // 4 x 64 cols

    // MODE 2 prologue: reciprocal row sums for this CTA's 128 rows
    // (fixed-order 64-term sum -> deterministic). Covered by iter-0 barrier.
    if (MODE == 2 && tid < 128) {
        const float4* pp = reinterpret_cast<const float4*>(
            part + (size_t)(bm + tid) * 64);
        float s = 0.0f;
        #pragma unroll
        for (int i = 0; i < 16; i++) {
            float4 v = pp[i];
            s += (v.x + v.y) + (v.z + v.w);
        }
        rsm[tid] = 1.0f / s;
    }

    float acc[4][8][4];
    #pragma unroll
    for (int mi = 0; mi < 4; mi++)
        #pragma unroll
        for (int ni = 0; ni < 8; ni++)
            #pragma unroll
            for (int r = 0; r < 4; r++) acc[mi][ni][r] = 0.0f;

    const uint32_t smb = smem_u32(sm);
    const int lrow = tid >> 3;          // 0..31
    const int lseg = tid & 7;

    auto load_stage = [&](int chunk) {
        const int s  = chunk % STG;
        const int k0 = chunk * 64;
        const uint32_t sa = smb + s * (STW * 4);
        const uint32_t sb = sa + OPWA * 4;
        #pragma unroll
        for (int p = 0; p < 4; p++) {            // A: 128 rows
            const int row  = lrow + p * 32;
            const int segS = lseg ^ (row & 7);
            const uint32_t so = (uint32_t)(row * 128 + segS * 16);
            cp16(sa + so, A + (size_t)(bm + row) * K + k0 + lseg * 8);
        }
        #pragma unroll
        for (int p = 0; p < 8; p++) {            // B: 256 rows
            const int row  = lrow + p * 32;
            const int segS = lseg ^ (row & 7);
            const uint32_t so = (uint32_t)(row * 128 + segS * 16);
            cp16(sb + so, B + (size_t)(bn + row) * K + k0 + lseg * 8);
        }
        cp_commit();
    };

    const int NT = K >> 6;

    load_stage(0);
    load_stage(1);

    for (int i = 0; i < NT; i++) {
        const int s = i % STG;
        cp_wait<1>();
        __syncthreads();

        if (i + 2 < NT) load_stage(i + 2);
        else            cp_commit();

        const uint32_t* As  = sm + s * STW;
        const uint32_t* Bsm = As + OPWA;
        const int swz = 4 * g;

        #pragma unroll
        for (int ksi = 0; ksi < 4; ksi++) {
            const int c0 = (ksi * 8 + t)     ^ swz;
            const int c2 = (ksi * 8 + t + 4) ^ swz;

            uint32_t af[4][4];
            #pragma unroll
            for (int mi = 0; mi < 4; mi++) {
                const uint32_t* base = As + (wm * 64 + mi * 16 + g) * 32;
                af[mi][0] = base[c0];
                af[mi][1] = base[8 * 32 + c0];
                af[mi][2] = base[c2];
                af[mi][3] = base[8 * 32 + c2];
            }
            uint32_t bf[8][2];
            #pragma unroll
            for (int ni = 0; ni < 8; ni++) {
                const uint32_t* base = Bsm + (wn * 64 + ni * 8 + g) * 32;
                bf[ni][0] = base[c0];
                bf[ni][1] = base[c2];
            }
            #pragma unroll
            for (int mi = 0; mi < 4; mi++)
                #pragma unroll
                for (int ni = 0; ni < 8; ni++)
                    mma_f16(acc[mi][ni][0], acc[mi][ni][1],
                            acc[mi][ni][2], acc[mi][ni][3],
                            af[mi][0], af[mi][1], af[mi][2], af[mi][3],
                            bf[ni][0], bf[ni][1]);
        }
    }

    // ---- epilogue ----
    if (MODE == 0) {
        __half* C = (__half*)Cv;
        #pragma unroll
        for (int mi = 0; mi < 4; mi++) {
            const int row = bm + wm * 64 + mi * 16 + g;
            #pragma unroll
            for (int ni = 0; ni < 8; ni++) {
                const int col = bn + wn * 64 + ni * 8 + 2 * t;
                *reinterpret_cast<__half2*>(&C[(size_t)row * N + col]) =
                    __floats2half2_rn(acc[mi][ni][0], acc[mi][ni][1]);
                *reinterpret_cast<__half2*>(&C[(size_t)(row + 8) * N + col]) =
                    __floats2half2_rn(acc[mi][ni][2], acc[mi][ni][3]);
            }
        }
    } else if (MODE == 1) {
        __half* C = (__half*)Cv;
        const float aL = alpha * 1.4426950408889634f;   // alpha * log2(e)
        #pragma unroll
        for (int mi = 0; mi < 4; mi++) {
            const int row = bm + wm * 64 + mi * 16 + g;
            float sr0 = 0.0f, sr1 = 0.0f;
            #pragma unroll
            for (int ni = 0; ni < 8; ni++) {
                const int col = bn + wn * 64 + ni * 8 + 2 * t;
                float v0, v1, v2, v3;
                if (ni & 1) {                 // FMA pipe
                    v0 = ex2_fma(acc[mi][ni][0] * aL);
                    v1 = ex2_fma(acc[mi][ni][1] * aL);
                    v2 = ex2_fma(acc[mi][ni][2] * aL);
                    v3 = ex2_fma(acc[mi][ni][3] * aL);
                } else {                      // MUFU pipe
                    v0 = ex2_mufu(acc[mi][ni][0] * aL);
                    v1 = ex2_mufu(acc[mi][ni][1] * aL);
                    v2 = ex2_mufu(acc[mi][ni][2] * aL);
                    v3 = ex2_mufu(acc[mi][ni][3] * aL);
                }
                *reinterpret_cast<__half2*>(&C[(size_t)row * N + col]) =
                    __floats2half2_rn(v0, v1);
                *reinterpret_cast<__half2*>(&C[(size_t)(row + 8) * N + col]) =
                    __floats2half2_rn(v2, v3);
                sr0 += v0 + v1;
                sr1 += v2 + v3;
            }
            // sum over the 4 t-lanes (same g)
            sr0 += __shfl_xor_sync(0xFFFFFFFF, sr0, 1);
            sr0 += __shfl_xor_sync(0xFFFFFFFF, sr0, 2);
            sr1 += __shfl_xor_sync(0xFFFFFFFF, sr1, 1);
            sr1 += __shfl_xor_sync(0xFFFFFFFF, sr1, 2);
            if (t == 0) {
                part[(size_t)row * 64 + bx * 4 + wn]       = sr0;
                part[(size_t)(row + 8) * 64 + bx * 4 + wn] = sr1;
            }
        }
    } else {
        float* C = (float*)Cv;
        #pragma unroll
        for (int mi = 0; mi < 4; mi++) {
            const int lr  = wm * 64 + mi * 16 + g;
            const int row = bm + lr;
            const float s0 = rsm[lr];
            const float s1 = rsm[lr + 8];
            #pragma unroll
            for (int ni = 0; ni < 8; ni++) {
                const int col = bn + wn * 64 + ni * 8 + 2 * t;
                *reinterpret_cast<float2*>(&C[(size_t)row * N + col]) =
                    make_float2(acc[mi][ni][0] * s0, acc[mi][ni][1] * s0);
                *reinterpret_cast<float2*>(&C[(size_t)(row + 8) * N + col]) =
                    make_float2(acc[mi][ni][2] * s1, acc[mi][ni][3] * s1);
            }
        }
    }
}

// Fused Q/K/V projections (fp16 out), blockIdx.z selects weight/output.
__global__ void __launch_bounds__(256, 1) proj_k(
    const __half* __restrict__ Xh,
    const __half* __restrict__ B0, const __half* __restrict__ B1,
    const __half* __restrict__ B2,
    __half* __restrict__ C0, __half* __restrict__ C1, __half* __restrict__ C2)
{
    const int z = blockIdx.z;
    const __half* B = (z == 0) ? B0 : (z == 1) ? B1 : B2;
    __half*       C = (z == 0) ? C0 : (z == 1) ? C1 : C2;
    gemm_body<0>(Xh, B, C, EMB, EMB, 1.0f, nullptr,
                 blockIdx.y * 128, blockIdx.x * 256, blockIdx.x);
}

// Score GEMM with fused exp + partial row sums.
__global__ void __launch_bounds__(256, 1) score_k(
    const __half* __restrict__ Q, const __half* __restrict__ Kh,
    __half* __restrict__ Sh, float* __restrict__ part)
{
    gemm_body<1>(Q, Kh, Sh, SEQ, EMB, 0.03125f, part,
                 blockIdx.y * 128, blockIdx.x * 256, blockIdx.x);
}

// PV GEMM; reciprocal row sums computed in-kernel from partials.
__global__ void __launch_bounds__(256, 1) pv_k(
    const __half* __restrict__ Sh, const __half* __restrict__ Vt,
    float* __restrict__ out, float* __restrict__ part)
{
    gemm_body<2>(Sh, Vt, out, EMB, SEQ, 1.0f, part,
                 blockIdx.y * 128, blockIdx.x * 256, blockIdx.x);
}

// ---------------------------------------------------------------------------
// Fused prep: z<3 -> transpose+convert weight z; z==3 -> convert x to fp16.
// grid (32, 32, 4), block (32, 8).
// ---------------------------------------------------------------------------
__global__ void __launch_bounds__(256) prep_k(
    const float* __restrict__ x,
    const float* __restrict__ Wq, const float* __restrict__ Wk,
    const float* __restrict__ Wv,
    __half* __restrict__ Xh,
    __half* __restrict__ Tq, __half* __restrict__ Tk, __half* __restrict__ Tv)
{
    const int z = blockIdx.z;
    const int xx = threadIdx.x, yy = threadIdx.y;   // 32 x 8

    if (z == 3) {
        const int bx = blockIdx.x * 32, by = blockIdx.y * 128;
        #pragma unroll
        for (int j = 0; j < 16; j++) {
            const int row = by + yy + j * 8;
            const int col = bx + xx;
            Xh[(size_t)row * EMB + col] =
                __float2half(x[(size_t)row * EMB + col]);
        }
        return;
    }

    __shared__ float tbuf[32][33];
    const float* in = (z == 0) ? Wq : (z == 1) ? Wk : Wv;
    __half*     out = (z == 0) ? Tq : (z == 1) ? Tk : Tv;

    const int bx = blockIdx.x * 32, by = blockIdx.y * 32;
    #pragma unroll
    for (int j = 0; j < 32; j += 8)
        tbuf[yy + j][xx] = in[(size_t)(by + yy + j) * EMB + bx + xx];
    __syncthreads();
    #pragma unroll
    for (int j = 0; j < 32; j += 8)
        out[(size_t)(bx + yy + j) * EMB + by + xx] =
            __float2half(tbuf[xx][yy + j]);
}

// ---------------------------------------------------------------------------
// fp16 transpose (V -> V^T)
// ---------------------------------------------------------------------------
__global__ void __launch_bounds__(256) htrans_k(const __half* __restrict__ in,
                                                __half* __restrict__ out,
                                                int R, int C)
{
    __shared__ __half t[32][34];
    const int bx = blockIdx.x * 32, by = blockIdx.y * 32;
    const int x = threadIdx.x, y = threadIdx.y;
    #pragma unroll
    for (int j = 0; j < 32; j += 8)
        t[y + j][x] = in[(size_t)(by + y + j) * C + bx + x];
    __syncthreads();
    #pragma unroll
    for (int j = 0; j < 32; j += 8)
        out[(size_t)(bx + y + j) * R + by + x] = t[x][y + j];
}

// ---------------------------------------------------------------------------
extern "C" void kernel_launch(void* const* d_in, const int* in_sizes, int n_in,
                              void* d_out, int out_size)
{
    const float* x  = (const float*)d_in[0];
    const float* Wq = (const float*)d_in[1];
    const float* Wk = (const float*)d_in[2];
    const float* Wv = (const float*)d_in[3];
    float* out = (float*)d_out;

    __half *Xh, *Wqt, *Wkt, *Wvt, *Qh, *Kh, *Vh, *Vt, *Sh;
    float *Part;
    cudaGetSymbolAddress((void**)&Xh,  g_Xh);
    cudaGetSymbolAddress((void**)&Wqt, g_Wqt);
    cudaGetSymbolAddress((void**)&Wkt, g_Wkt);
    cudaGetSymbolAddress((void**)&Wvt, g_Wvt);
    cudaGetSymbolAddress((void**)&Qh,  g_Qh);
    cudaGetSymbolAddress((void**)&Kh,  g_Kh);
    cudaGetSymbolAddress((void**)&Vh,  g_Vh);
    cudaGetSymbolAddress((void**)&Vt,  g_Vt);
    cudaGetSymbolAddress((void**)&Sh,  g_Sh);
    cudaGetSymbolAddress((void**)&Part, g_part);

    cudaFuncSetAttribute(proj_k,
        cudaFuncAttributeMaxDynamicSharedMemorySize, GEMM_DYNSMEM);
    cudaFuncSetAttribute(score_k,
        cudaFuncAttributeMaxDynamicSharedMemorySize, GEMM_DYNSMEM);
    cudaFuncSetAttribute(pv_k,
        cudaFuncAttributeMaxDynamicSharedMemorySize, GEMM_DYNSMEM);

    // Fused prep: x convert + 3 weight transposes in one launch.
    prep_k<<<dim3(32, 32, 4), dim3(32, 8)>>>(x, Wq, Wk, Wv, Xh, Wqt, Wkt, Wvt);

    const dim3 blk(256);
    const dim3 gProj(EMB / 256, SEQ / 128, 3);   // 4 x 32 x 3
    const dim3 gScore(SEQ / 256, SEQ / 128);     // 16 x 32
    const dim3 gPV  (EMB / 256, SEQ / 128);      // 4 x 32
    const dim3 tblk(32, 8);
    const dim3 gVt(EMB / 32, SEQ / 32);

    // Projections (NT, fp16 out).
    proj_k<<<gProj, blk, GEMM_DYNSMEM>>>(Xh, Wqt, Wkt, Wvt, Qh, Kh, Vh);

    // V^T for the NT PV GEMM.
    htrans_k<<<gVt, tblk>>>(Vh, Vt, SEQ, EMB);

    // Scores + fused exp (fp16 out) + deterministic partial row sums.
    score_k<<<gScore, blk, GEMM_DYNSMEM>>>(Qh, Kh, Sh, Part);

    // Output: out = diag(1/rowsum) * (expS @ Vt^T); rsum fused in prologue.
    pv_k<<<gPV, blk, GEMM_DYNSMEM>>>(Sh, Vt, out, Part);
}

// round 11
// speedup vs baseline: 1.0802x; 1.0802x over previous
#include <cuda_runtime.h>
#include <cuda_fp16.h>
#include <cstdint>

#define SEQ 4096
#define EMB 1024

// ---------------- scratch (static, allocation-free) ----------------
__device__ __half g_Xh [(size_t)SEQ * EMB];
__device__ __half g_Wqt[(size_t)EMB * EMB];
__device__ __half g_Wkt[(size_t)EMB * EMB];
__device__ __half g_Wvt[(size_t)EMB * EMB];
__device__ __half g_Qh [(size_t)SEQ * EMB];
__device__ __half g_Kh [(size_t)SEQ * EMB];
__device__ __half g_Vt [(size_t)EMB * SEQ];
__device__ __half g_Sh [(size_t)SEQ * SEQ];
__device__ float  g_part[(size_t)SEQ * 64];   // per (row, colCTA*2+wn) partials

// ---------------- helpers ----------------
__device__ __forceinline__ uint32_t smem_u32(const void* p) {
    return (uint32_t)__cvta_generic_to_shared(p);
}
__device__ __forceinline__ void cp16(uint32_t s, const void* g) {
    asm volatile("cp.async.cg.shared.global [%0], [%1], 16;" :: "r"(s), "l"(g));
}
__device__ __forceinline__ void cp_commit() {
    asm volatile("cp.async.commit_group;" ::: "memory");
}
template <int N>
__device__ __forceinline__ void cp_wait() {
    asm volatile("cp.async.wait_group %0;" :: "n"(N) : "memory");
}
__device__ __forceinline__ float ex2_mufu(float y) {
    float r;
    asm("ex2.approx.ftz.f32 %0, %1;" : "=f"(r) : "f"(y));
    return r;
}
// exact-split exp2 on the FMA pipe (y = n + f, f in [-.5,.5], degree-5 poly)
__device__ __forceinline__ float ex2_fma(float y) {
    const float MAGIC = 12582912.0f;          // 1.5 * 2^23
    float tm = __fadd_rn(y, MAGIC);
    float f  = __fadd_rn(y, -__fadd_rn(tm, -MAGIC));
    int   eb = (__float_as_int(tm) << 23) + 0x3F800000;
    float pl = 0.0013333558f;
    pl = fmaf(pl, f, 0.0096181291f);
    pl = fmaf(pl, f, 0.0555041087f);
    pl = fmaf(pl, f, 0.2402265069f);
    pl = fmaf(pl, f, 0.6931471806f);
    pl = fmaf(pl, f, 1.0f);
    return __int_as_float(eb) * pl;
}
// m16n8k16 fp16 MMA, fp32 accumulate
__device__ __forceinline__ void mma_f16(
    float& c0, float& c1, float& c2, float& c3,
    uint32_t a0, uint32_t a1, uint32_t a2, uint32_t a3,
    uint32_t b0, uint32_t b1)
{
    asm volatile(
        "mma.sync.aligned.m16n8k16.row.col.f32.f16.f16.f32 "
        "{%0,%1,%2,%3}, {%4,%5,%6,%7}, {%8,%9}, {%0,%1,%2,%3};"
        : "+f"(c0), "+f"(c1), "+f"(c2), "+f"(c3)
        : "r"(a0), "r"(a1), "r"(a2), "r"(a3), "r"(b0), "r"(b1));
}

// ---------------------------------------------------------------------------
// FP16 tensor-core NT GEMM: C[M,N] = f( A[M,K] @ B[N,K]^T )
// 128 threads (4 warps 2x2), warp tile 64x64, CTA tile 128x128, BK=64,
// 3-stage cp.async, one __syncthreads/iter, XOR-swizzled smem,
// scalar-LDS fragment loads (round-7/9 known-good mainloop).
// MODE 0: fp16 out (Q/K projections)
// MODE 1: Sh = fp16(exp(alpha*acc)); per-(row,warp) partial sums -> part
// MODE 2: fp32 out scaled by rsum computed in prologue from part
// MODE 3: fp16 TRANSPOSED out (V projection -> Vt[col*SEQ + row])
// ---------------------------------------------------------------------------
#define STG 3
#define OPW (128 * 32)                 // fp16x2 words per operand tile (16KB)
#define STW (2 * OPW)
#define GEMM_DYNSMEM (STG * STW * 4)   // 98304 bytes

template <int MODE>
__device__ __forceinline__ void gemm_body(
    const __half* __restrict__ A, const __half* __restrict__ B,
    void* __restrict__ Cv, int N, int K, float alpha,
    float* __restrict__ part, int bm, int bn, int bx)
{
    extern __shared__ uint32_t sm[];
    __shared__ float rsm[128];

    const int tid  = threadIdx.x;
    const int warp = tid >> 5;
    const int lane = tid & 31;
    const int g    = lane >> 2;
    const int t    = lane & 3;
    const int wm   = warp & 1;      // 2 x 64 rows
    const int wn   = warp >> 1;     // 2 x 64 cols

    // MODE 2 prologue: reciprocal row sums for this CTA's 128 rows
    // (fixed-order 64-term sum -> deterministic). Covered by iter-0 barrier.
    if (MODE == 2) {
        const float4* pp = reinterpret_cast<const float4*>(
            part + (size_t)(bm + tid) * 64);
        float s = 0.0f;
        #pragma unroll
        for (int i = 0; i < 16; i++) {
            float4 v = pp[i];
            s += (v.x + v.y) + (v.z + v.w);
        }
        rsm[tid] = 1.0f / s;
    }

    float acc[4][8][4];
    #pragma unroll
    for (int mi = 0; mi < 4; mi++)
        #pragma unroll
        for (int ni = 0; ni < 8; ni++)
            #pragma unroll
            for (int r = 0; r < 4; r++) acc[mi][ni][r] = 0.0f;

    const uint32_t smb = smem_u32(sm);
    const int lrow = tid >> 3;          // 0..15, 8 passes -> 128 rows
    const int lseg = tid & 7;

    auto load_stage = [&](int chunk) {
        const int s  = chunk % STG;
        const int k0 = chunk * 64;
        const uint32_t sa = smb + s * (STW * 4);
        const uint32_t sb = sa + OPW * 4;
        #pragma unroll
        for (int p = 0; p < 8; p++) {
            const int row  = lrow + p * 16;
            const int segS = lseg ^ (row & 7);
            const uint32_t so = (uint32_t)(row * 128 + segS * 16);
            cp16(sa + so, A + (size_t)(bm + row) * K + k0 + lseg * 8);
            cp16(sb + so, B + (size_t)(bn + row) * K + k0 + lseg * 8);
        }
        cp_commit();
    };

    const int NT = K >> 6;

    load_stage(0);
    load_stage(1);

    for (int i = 0; i < NT; i++) {
        const int s = i % STG;
        cp_wait<1>();
        __syncthreads();

        if (i + 2 < NT) load_stage(i + 2);
        else            cp_commit();

        const uint32_t* As  = sm + s * STW;
        const uint32_t* Bsm = As + OPW;
        const int swz = 4 * g;

        #pragma unroll
        for (int ksi = 0; ksi < 4; ksi++) {
            const int c0 = (ksi * 8 + t)     ^ swz;
            const int c2 = (ksi * 8 + t + 4) ^ swz;

            uint32_t af[4][4];
            #pragma unroll
            for (int mi = 0; mi < 4; mi++) {
                const uint32_t* base = As + (wm * 64 + mi * 16 + g) * 32;
                af[mi][0] = base[c0];
                af[mi][1] = base[8 * 32 + c0];
                af[mi][2] = base[c2];
                af[mi][3] = base[8 * 32 + c2];
            }
            uint32_t bf[8][2];
            #pragma unroll
            for (int ni = 0; ni < 8; ni++) {
                const uint32_t* base = Bsm + (wn * 64 + ni * 8 + g) * 32;
                bf[ni][0] = base[c0];
                bf[ni][1] = base[c2];
            }
            #pragma unroll
            for (int mi = 0; mi < 4; mi++)
                #pragma unroll
                for (int ni = 0; ni < 8; ni++)
                    mma_f16(acc[mi][ni][0], acc[mi][ni][1],
                            acc[mi][ni][2], acc[mi][ni][3],
                            af[mi][0], af[mi][1], af[mi][2], af[mi][3],
                            bf[ni][0], bf[ni][1]);
        }
    }

    // ---- epilogue ----
    if (MODE == 0) {
        __half* C = (__half*)Cv;
        #pragma unroll
        for (int mi = 0; mi < 4; mi++) {
            const int row = bm + wm * 64 + mi * 16 + g;
            #pragma unroll
            for (int ni = 0; ni < 8; ni++) {
                const int col = bn + wn * 64 + ni * 8 + 2 * t;
                *reinterpret_cast<__half2*>(&C[(size_t)row * N + col]) =
                    __floats2half2_rn(acc[mi][ni][0], acc[mi][ni][1]);
                *reinterpret_cast<__half2*>(&C[(size_t)(row + 8) * N + col]) =
                    __floats2half2_rn(acc[mi][ni][2], acc[mi][ni][3]);
            }
        }
    } else if (MODE == 1) {
        __half* C = (__half*)Cv;
        const float aL = alpha * 1.4426950408889634f;   // alpha * log2(e)
        #pragma unroll
        for (int mi = 0; mi < 4; mi++) {
            const int row = bm + wm * 64 + mi * 16 + g;
            float sr0 = 0.0f, sr1 = 0.0f;
            #pragma unroll
            for (int ni = 0; ni < 8; ni++) {
                const int col = bn + wn * 64 + ni * 8 + 2 * t;
                float v0, v1, v2, v3;
                if (ni & 1) {                 // FMA pipe
                    v0 = ex2_fma(acc[mi][ni][0] * aL);
                    v1 = ex2_fma(acc[mi][ni][1] * aL);
                    v2 = ex2_fma(acc[mi][ni][2] * aL);
                    v3 = ex2_fma(acc[mi][ni][3] * aL);
                } else {                      // MUFU pipe
                    v0 = ex2_mufu(acc[mi][ni][0] * aL);
                    v1 = ex2_mufu(acc[mi][ni][1] * aL);
                    v2 = ex2_mufu(acc[mi][ni][2] * aL);
                    v3 = ex2_mufu(acc[mi][ni][3] * aL);
                }
                *reinterpret_cast<__half2*>(&C[(size_t)row * N + col]) =
                    __floats2half2_rn(v0, v1);
                *reinterpret_cast<__half2*>(&C[(size_t)(row + 8) * N + col]) =
                    __floats2half2_rn(v2, v3);
                sr0 += v0 + v1;
                sr1 += v2 + v3;
            }
            // sum over the 4 t-lanes (same g)
            sr0 += __shfl_xor_sync(0xFFFFFFFF, sr0, 1);
            sr0 += __shfl_xor_sync(0xFFFFFFFF, sr0, 2);
            sr1 += __shfl_xor_sync(0xFFFFFFFF, sr1, 1);
            sr1 += __shfl_xor_sync(0xFFFFFFFF, sr1, 2);
            if (t == 0) {
                part[(size_t)row * 64 + bx * 2 + wn]       = sr0;
                part[(size_t)(row + 8) * 64 + bx * 2 + wn] = sr1;
            }
        }
    } else if (MODE == 2) {
        float* C = (float*)Cv;
        #pragma unroll
        for (int mi = 0; mi < 4; mi++) {
            const int lr  = wm * 64 + mi * 16 + g;
            const int row = bm + lr;
            const float s0 = rsm[lr];
            const float s1 = rsm[lr + 8];
            #pragma unroll
            for (int ni = 0; ni < 8; ni++) {
                const int col = bn + wn * 64 + ni * 8 + 2 * t;
                *reinterpret_cast<float2*>(&C[(size_t)row * N + col]) =
                    make_float2(acc[mi][ni][0] * s0, acc[mi][ni][1] * s0);
                *reinterpret_cast<float2*>(&C[(size_t)(row + 8) * N + col]) =
                    make_float2(acc[mi][ni][2] * s1, acc[mi][ni][3] * s1);
            }
        }
    } else {
        // MODE 3: transposed fp16 store -> Vt[col * SEQ + row].
        // Same rounded values as MODE 0 would produce; only layout differs.
        __half* C = (__half*)Cv;
        #pragma unroll
        for (int mi = 0; mi < 4; mi++) {
            const int row = bm + wm * 64 + mi * 16 + g;
            #pragma unroll
            for (int ni = 0; ni < 8; ni++) {
                const int col = bn + wn * 64 + ni * 8 + 2 * t;
                C[(size_t)col * SEQ + row]           = __float2half(acc[mi][ni][0]);
                C[(size_t)(col + 1) * SEQ + row]     = __float2half(acc[mi][ni][1]);
                C[(size_t)col * SEQ + row + 8]       = __float2half(acc[mi][ni][2]);
                C[(size_t)(col + 1) * SEQ + row + 8] = __float2half(acc[mi][ni][3]);
            }
        }
    }
}

// Fused Q/K/V projections, blockIdx.z selects weight/output.
// z=0,1: normal fp16 out (Q, K). z=2: transposed fp16 out (Vt).
__global__ void __launch_bounds__(128, 2) proj_k(
    const __half* __restrict__ Xh,
    const __half* __restrict__ B0, const __half* __restrict__ B1,
    const __half* __restrict__ B2,
    __half* __restrict__ C0, __half* __restrict__ C1, __half* __restrict__ Vt)
{
    const int z = blockIdx.z;
    if (z == 2) {
        gemm_body<3>(Xh, B2, Vt, EMB, EMB, 1.0f, nullptr,
                     blockIdx.y * 128, blockIdx.x * 128, blockIdx.x);
    } else {
        const __half* B = (z == 0) ? B0 : B1;
        __half*       C = (z == 0) ? C0 : C1;
        gemm_body<0>(Xh, B, C, EMB, EMB, 1.0f, nullptr,
                     blockIdx.y * 128, blockIdx.x * 128, blockIdx.x);
    }
}

// Score GEMM with fused exp + partial row sums.
__global__ void __launch_bounds__(128, 2) score_k(
    const __half* __restrict__ Q, const __half* __restrict__ Kh,
    __half* __restrict__ Sh, float* __restrict__ part)
{
    gemm_body<1>(Q, Kh, Sh, SEQ, EMB, 0.03125f, part,
                 blockIdx.y * 128, blockIdx.x * 128, blockIdx.x);
}

// PV GEMM; reciprocal row sums computed in-kernel from partials.
__global__ void __launch_bounds__(128, 2) pv_k(
    const __half* __restrict__ Sh, const __half* __restrict__ Vt,
    float* __restrict__ out, float* __restrict__ part)
{
    gemm_body<2>(Sh, Vt, out, EMB, SEQ, 1.0f, part,
                 blockIdx.y * 128, blockIdx.x * 128, blockIdx.x);
}

// ---------------------------------------------------------------------------
// Fused prep: z<3 -> transpose+convert weight z; z==3 -> convert x to fp16.
// grid (32, 32, 4), block (32, 8).
// ---------------------------------------------------------------------------
__global__ void __launch_bounds__(256) prep_k(
    const float* __restrict__ x,
    const float* __restrict__ Wq, const float* __restrict__ Wk,
    const float* __restrict__ Wv,
    __half* __restrict__ Xh,
    __half* __restrict__ Tq, __half* __restrict__ Tk, __half* __restrict__ Tv)
{
    const int z = blockIdx.z;
    const int xx = threadIdx.x, yy = threadIdx.y;   // 32 x 8

    if (z == 3) {
        const int bx = blockIdx.x * 32, by = blockIdx.y * 128;
        #pragma unroll
        for (int j = 0; j < 16; j++) {
            const int row = by + yy + j * 8;
            const int col = bx + xx;
            Xh[(size_t)row * EMB + col] =
                __float2half(x[(size_t)row * EMB + col]);
        }
        return;
    }

    __shared__ float tbuf[32][33];
    const float* in = (z == 0) ? Wq : (z == 1) ? Wk : Wv;
    __half*     out = (z == 0) ? Tq : (z == 1) ? Tk : Tv;

    const int bx = blockIdx.x * 32, by = blockIdx.y * 32;
    #pragma unroll
    for (int j = 0; j < 32; j += 8)
        tbuf[yy + j][xx] = in[(size_t)(by + yy + j) * EMB + bx + xx];
    __syncthreads();
    #pragma unroll
    for (int j = 0; j < 32; j += 8)
        out[(size_t)(bx + yy + j) * EMB + by + xx] =
            __float2half(tbuf[xx][yy + j]);
}

// ---------------------------------------------------------------------------
extern "C" void kernel_launch(void* const* d_in, const int* in_sizes, int n_in,
                              void* d_out, int out_size)
{
    const float* x  = (const float*)d_in[0];
    const float* Wq = (const float*)d_in[1];
    const float* Wk = (const float*)d_in[2];
    const float* Wv = (const float*)d_in[3];
    float* out = (float*)d_out;

    __half *Xh, *Wqt, *Wkt, *Wvt, *Qh, *Kh, *Vt, *Sh;
    float *Part;
    cudaGetSymbolAddress((void**)&Xh,  g_Xh);
    cudaGetSymbolAddress((void**)&Wqt, g_Wqt);
    cudaGetSymbolAddress((void**)&Wkt, g_Wkt);
    cudaGetSymbolAddress((void**)&Wvt, g_Wvt);
    cudaGetSymbolAddress((void**)&Qh,  g_Qh);
    cudaGetSymbolAddress((void**)&Kh,  g_Kh);
    cudaGetSymbolAddress((void**)&Vt,  g_Vt);
    cudaGetSymbolAddress((void**)&Sh,  g_Sh);
    cudaGetSymbolAddress((void**)&Part, g_part);

    cudaFuncSetAttribute(proj_k,
        cudaFuncAttributeMaxDynamicSharedMemorySize, GEMM_DYNSMEM);
    cudaFuncSetAttribute(score_k,
        cudaFuncAttributeMaxDynamicSharedMemorySize, GEMM_DYNSMEM);
    cudaFuncSetAttribute(pv_k,
        cudaFuncAttributeMaxDynamicSharedMemorySize, GEMM_DYNSMEM);

    // Fused prep: x convert + 3 weight transposes in one launch.
    prep_k<<<dim3(32, 32, 4), dim3(32, 8)>>>(x, Wq, Wk, Wv, Xh, Wqt, Wkt, Wvt);

    const dim3 blk(128);
    const dim3 gProj(EMB / 128, SEQ / 128, 3);   // 8 x 32 x 3
    const dim3 gScore(SEQ / 128, SEQ / 128);     // 32 x 32
    const dim3 gPV  (EMB / 128, SEQ / 128);      // 8 x 32

    // Projections: Q/K fp16 out; V written directly transposed (Vt).
    proj_k<<<gProj, blk, GEMM_DYNSMEM>>>(Xh, Wqt, Wkt, Wvt, Qh, Kh, Vt);

    // Scores + fused exp (fp16 out) + deterministic partial row sums.
    score_k<<<gScore, blk, GEMM_DYNSMEM>>>(Qh, Kh, Sh, Part);

    // Output: out = diag(1/rowsum) * (expS @ Vt^T); rsum fused in prologue.
    pv_k<<<gPV, blk, GEMM_DYNSMEM>>>(Sh, Vt, out, Part);
}

// round 12
// speedup vs baseline: 1.1797x; 1.0921x over previous
#include <cuda_runtime.h>
#include <cuda_fp16.h>
#include <cstdint>

#define SEQ 4096
#define EMB 1024

// ---------------- scratch (static, allocation-free) ----------------
__device__ __half g_Xh [(size_t)SEQ * EMB];
__device__ __half g_Wqh[(size_t)EMB * EMB];   // fp16(Wq), row-major
__device__ __half g_Wkh[(size_t)EMB * EMB];   // fp16(Wk), row-major
__device__ __half g_Wvt[(size_t)EMB * EMB];   // fp16(Wv^T)
__device__ __half g_M  [(size_t)EMB * EMB];   // Wq @ Wk^T
__device__ __half g_Tt [(size_t)SEQ * EMB];   // (M @ X^T)^T  == "K-like" operand
__device__ __half g_Vt [(size_t)EMB * SEQ];
__device__ __half g_Sh [(size_t)SEQ * SEQ];
__device__ float  g_part[(size_t)SEQ * 64];   // per (row, colCTA*2+wn) partials

// ---------------- helpers ----------------
__device__ __forceinline__ uint32_t smem_u32(const void* p) {
    return (uint32_t)__cvta_generic_to_shared(p);
}
__device__ __forceinline__ void cp16(uint32_t s, const void* g) {
    asm volatile("cp.async.cg.shared.global [%0], [%1], 16;" :: "r"(s), "l"(g));
}
__device__ __forceinline__ void cp_commit() {
    asm volatile("cp.async.commit_group;" ::: "memory");
}
template <int N>
__device__ __forceinline__ void cp_wait() {
    asm volatile("cp.async.wait_group %0;" :: "n"(N) : "memory");
}
__device__ __forceinline__ float ex2_mufu(float y) {
    float r;
    asm("ex2.approx.ftz.f32 %0, %1;" : "=f"(r) : "f"(y));
    return r;
}
// exact-split exp2 on the FMA pipe (y = n + f, f in [-.5,.5], degree-5 poly)
__device__ __forceinline__ float ex2_fma(float y) {
    const float MAGIC = 12582912.0f;          // 1.5 * 2^23
    float tm = __fadd_rn(y, MAGIC);
    float f  = __fadd_rn(y, -__fadd_rn(tm, -MAGIC));
    int   eb = (__float_as_int(tm) << 23) + 0x3F800000;
    float pl = 0.0013333558f;
    pl = fmaf(pl, f, 0.0096181291f);
    pl = fmaf(pl, f, 0.0555041087f);
    pl = fmaf(pl, f, 0.2402265069f);
    pl = fmaf(pl, f, 0.6931471806f);
    pl = fmaf(pl, f, 1.0f);
    return __int_as_float(eb) * pl;
}
// m16n8k16 fp16 MMA, fp32 accumulate
__device__ __forceinline__ void mma_f16(
    float& c0, float& c1, float& c2, float& c3,
    uint32_t a0, uint32_t a1, uint32_t a2, uint32_t a3,
    uint32_t b0, uint32_t b1)
{
    asm volatile(
        "mma.sync.aligned.m16n8k16.row.col.f32.f16.f16.f32 "
        "{%0,%1,%2,%3}, {%4,%5,%6,%7}, {%8,%9}, {%0,%1,%2,%3};"
        : "+f"(c0), "+f"(c1), "+f"(c2), "+f"(c3)
        : "r"(a0), "r"(a1), "r"(a2), "r"(a3), "r"(b0), "r"(b1));
}

// ---------------------------------------------------------------------------
// FP16 tensor-core NT GEMM: C[M,N] = f( A[M,K] @ B[N,K]^T )
// 128 threads (4 warps 2x2), warp tile 64x64, CTA tile 128x128, BK=64,
// 3-stage cp.async, one __syncthreads/iter, XOR-swizzled smem,
// scalar-LDS fragment loads (known-good mainloop).
// MODE 0: fp16 out
// MODE 1: Sh = fp16(exp(alpha*acc)); per-(row,warp) partial sums -> part
// MODE 2: fp32 out scaled by rsum computed in prologue from part
// MODE 3: fp16 TRANSPOSED out: C[col*mtot + row]  (mtot = total M dim)
// ---------------------------------------------------------------------------
#define STG 3
#define OPW (128 * 32)                 // fp16x2 words per operand tile (16KB)
#define STW (2 * OPW)
#define GEMM_DYNSMEM (STG * STW * 4)   // 98304 bytes

template <int MODE>
__device__ __forceinline__ void gemm_body(
    const __half* __restrict__ A, const __half* __restrict__ B,
    void* __restrict__ Cv, int N, int K, float alpha,
    float* __restrict__ part, int bm, int bn, int bx, int mtot)
{
    extern __shared__ uint32_t sm[];
    __shared__ float rsm[128];

    const int tid  = threadIdx.x;
    const int warp = tid >> 5;
    const int lane = tid & 31;
    const int g    = lane >> 2;
    const int t    = lane & 3;
    const int wm   = warp & 1;      // 2 x 64 rows
    const int wn   = warp >> 1;     // 2 x 64 cols

    // MODE 2 prologue: reciprocal row sums for this CTA's 128 rows
    // (fixed-order 64-term sum -> deterministic). Covered by iter-0 barrier.
    if (MODE == 2) {
        const float4* pp = reinterpret_cast<const float4*>(
            part + (size_t)(bm + tid) * 64);
        float s = 0.0f;
        #pragma unroll
        for (int i = 0; i < 16; i++) {
            float4 v = pp[i];
            s += (v.x + v.y) + (v.z + v.w);
        }
        rsm[tid] = 1.0f / s;
    }

    float acc[4][8][4];
    #pragma unroll
    for (int mi = 0; mi < 4; mi++)
        #pragma unroll
        for (int ni = 0; ni < 8; ni++)
            #pragma unroll
            for (int r = 0; r < 4; r++) acc[mi][ni][r] = 0.0f;

    const uint32_t smb = smem_u32(sm);
    const int lrow = tid >> 3;          // 0..15, 8 passes -> 128 rows
    const int lseg = tid & 7;

    auto load_stage = [&](int chunk) {
        const int s  = chunk % STG;
        const int k0 = chunk * 64;
        const uint32_t sa = smb + s * (STW * 4);
        const uint32_t sb = sa + OPW * 4;
        #pragma unroll
        for (int p = 0; p < 8; p++) {
            const int row  = lrow + p * 16;
            const int segS = lseg ^ (row & 7);
            const uint32_t so = (uint32_t)(row * 128 + segS * 16);
            cp16(sa + so, A + (size_t)(bm + row) * K + k0 + lseg * 8);
            cp16(sb + so, B + (size_t)(bn + row) * K + k0 + lseg * 8);
        }
        cp_commit();
    };

    const int NT = K >> 6;

    load_stage(0);
    load_stage(1);

    for (int i = 0; i < NT; i++) {
        const int s = i % STG;
        cp_wait<1>();
        __syncthreads();

        if (i + 2 < NT) load_stage(i + 2);
        else            cp_commit();

        const uint32_t* As  = sm + s * STW;
        const uint32_t* Bsm = As + OPW;
        const int swz = 4 * g;

        #pragma unroll
        for (int ksi = 0; ksi < 4; ksi++) {
            const int c0 = (ksi * 8 + t)     ^ swz;
            const int c2 = (ksi * 8 + t + 4) ^ swz;

            uint32_t af[4][4];
            #pragma unroll
            for (int mi = 0; mi < 4; mi++) {
                const uint32_t* base = As + (wm * 64 + mi * 16 + g) * 32;
                af[mi][0] = base[c0];
                af[mi][1] = base[8 * 32 + c0];
                af[mi][2] = base[c2];
                af[mi][3] = base[8 * 32 + c2];
            }
            uint32_t bf[8][2];
            #pragma unroll
            for (int ni = 0; ni < 8; ni++) {
                const uint32_t* base = Bsm + (wn * 64 + ni * 8 + g) * 32;
                bf[ni][0] = base[c0];
                bf[ni][1] = base[c2];
            }
            #pragma unroll
            for (int mi = 0; mi < 4; mi++)
                #pragma unroll
                for (int ni = 0; ni < 8; ni++)
                    mma_f16(acc[mi][ni][0], acc[mi][ni][1],
                            acc[mi][ni][2], acc[mi][ni][3],
                            af[mi][0], af[mi][1], af[mi][2], af[mi][3],
                            bf[ni][0], bf[ni][1]);
        }
    }

    // ---- epilogue ----
    if (MODE == 0) {
        __half* C = (__half*)Cv;
        #pragma unroll
        for (int mi = 0; mi < 4; mi++) {
            const int row = bm + wm * 64 + mi * 16 + g;
            #pragma unroll
            for (int ni = 0; ni < 8; ni++) {
                const int col = bn + wn * 64 + ni * 8 + 2 * t;
                *reinterpret_cast<__half2*>(&C[(size_t)row * N + col]) =
                    __floats2half2_rn(acc[mi][ni][0], acc[mi][ni][1]);
                *reinterpret_cast<__half2*>(&C[(size_t)(row + 8) * N + col]) =
                    __floats2half2_rn(acc[mi][ni][2], acc[mi][ni][3]);
            }
        }
    } else if (MODE == 1) {
        __half* C = (__half*)Cv;
        const float aL = alpha * 1.4426950408889634f;   // alpha * log2(e)
        #pragma unroll
        for (int mi = 0; mi < 4; mi++) {
            const int row = bm + wm * 64 + mi * 16 + g;
            float sr0 = 0.0f, sr1 = 0.0f;
            #pragma unroll
            for (int ni = 0; ni < 8; ni++) {
                const int col = bn + wn * 64 + ni * 8 + 2 * t;
                float v0, v1, v2, v3;
                if (ni & 1) {                 // FMA pipe
                    v0 = ex2_fma(acc[mi][ni][0] * aL);
                    v1 = ex2_fma(acc[mi][ni][1] * aL);
                    v2 = ex2_fma(acc[mi][ni][2] * aL);
                    v3 = ex2_fma(acc[mi][ni][3] * aL);
                } else {                      // MUFU pipe
                    v0 = ex2_mufu(acc[mi][ni][0] * aL);
                    v1 = ex2_mufu(acc[mi][ni][1] * aL);
                    v2 = ex2_mufu(acc[mi][ni][2] * aL);
                    v3 = ex2_mufu(acc[mi][ni][3] * aL);
                }
                *reinterpret_cast<__half2*>(&C[(size_t)row * N + col]) =
                    __floats2half2_rn(v0, v1);
                *reinterpret_cast<__half2*>(&C[(size_t)(row + 8) * N + col]) =
                    __floats2half2_rn(v2, v3);
                sr0 += v0 + v1;
                sr1 += v2 + v3;
            }
            // sum over the 4 t-lanes (same g)
            sr0 += __shfl_xor_sync(0xFFFFFFFF, sr0, 1);
            sr0 += __shfl_xor_sync(0xFFFFFFFF, sr0, 2);
            sr1 += __shfl_xor_sync(0xFFFFFFFF, sr1, 1);
            sr1 += __shfl_xor_sync(0xFFFFFFFF, sr1, 2);
            if (t == 0) {
                part[(size_t)row * 64 + bx * 2 + wn]       = sr0;
                part[(size_t)(row + 8) * 64 + bx * 2 + wn] = sr1;
            }
        }
    } else if (MODE == 2) {
        float* C = (float*)Cv;
        #pragma unroll
        for (int mi = 0; mi < 4; mi++) {
            const int lr  = wm * 64 + mi * 16 + g;
            const int row = bm + lr;
            const float s0 = rsm[lr];
            const float s1 = rsm[lr + 8];
            #pragma unroll
            for (int ni = 0; ni < 8; ni++) {
                const int col = bn + wn * 64 + ni * 8 + 2 * t;
                *reinterpret_cast<float2*>(&C[(size_t)row * N + col]) =
                    make_float2(acc[mi][ni][0] * s0, acc[mi][ni][1] * s0);
                *reinterpret_cast<float2*>(&C[(size_t)(row + 8) * N + col]) =
                    make_float2(acc[mi][ni][2] * s1, acc[mi][ni][3] * s1);
            }
        }
    } else {
        // MODE 3: transposed fp16 store -> C[col * mtot + row].
        __half* C = (__half*)Cv;
        #pragma unroll
        for (int mi = 0; mi < 4; mi++) {
            const int row = bm + wm * 64 + mi * 16 + g;
            #pragma unroll
            for (int ni = 0; ni < 8; ni++) {
                const int col = bn + wn * 64 + ni * 8 + 2 * t;
                C[(size_t)col * mtot + row]           = __float2half(acc[mi][ni][0]);
                C[(size_t)(col + 1) * mtot + row]     = __float2half(acc[mi][ni][1]);
                C[(size_t)col * mtot + row + 8]       = __float2half(acc[mi][ni][2]);
                C[(size_t)(col + 1) * mtot + row + 8] = __float2half(acc[mi][ni][3]);
            }
        }
    }
}

// Plain fp16-out GEMM (used for M = Wq @ Wk^T).
__global__ void __launch_bounds__(128, 2) gemm16_k(
    const __half* __restrict__ A, const __half* __restrict__ B,
    __half* __restrict__ C, int N, int K)
{
    gemm_body<0>(A, B, C, N, K, 1.0f, nullptr,
                 blockIdx.y * 128, blockIdx.x * 128, blockIdx.x, 0);
}

// Transposed-out GEMM (used for Tt and Vt).
__global__ void __launch_bounds__(128, 2) gemmT_k(
    const __half* __restrict__ A, const __half* __restrict__ B,
    __half* __restrict__ C, int N, int K)
{
    gemm_body<3>(A, B, C, N, K, 1.0f, nullptr,
                 blockIdx.y * 128, blockIdx.x * 128, blockIdx.x,
                 (int)gridDim.y * 128);
}

// Score GEMM with fused exp + partial row sums.
__global__ void __launch_bounds__(128, 2) score_k(
    const __half* __restrict__ Q, const __half* __restrict__ Kh,
    __half* __restrict__ Sh, float* __restrict__ part)
{
    gemm_body<1>(Q, Kh, Sh, SEQ, EMB, 0.03125f, part,
                 blockIdx.y * 128, blockIdx.x * 128, blockIdx.x, 0);
}

// PV GEMM; reciprocal row sums computed in-kernel from partials.
__global__ void __launch_bounds__(128, 2) pv_k(
    const __half* __restrict__ Sh, const __half* __restrict__ Vt,
    float* __restrict__ out, float* __restrict__ part)
{
    gemm_body<2>(Sh, Vt, out, EMB, SEQ, 1.0f, part,
                 blockIdx.y * 128, blockIdx.x * 128, blockIdx.x, 0);
}

// ---------------------------------------------------------------------------
// Fused prep: z=0 convert Wq; z=1 convert Wk; z=2 transpose Wv; z=3 convert x.
// grid (32, 32, 4), block (32, 8).
// ---------------------------------------------------------------------------
__global__ void __launch_bounds__(256) prep_k(
    const float* __restrict__ x,
    const float* __restrict__ Wq, const float* __restrict__ Wk,
    const float* __restrict__ Wv,
    __half* __restrict__ Xh,
    __half* __restrict__ Wqh, __half* __restrict__ Wkh,
    __half* __restrict__ Wvt)
{
    const int z = blockIdx.z;
    const int xx = threadIdx.x, yy = threadIdx.y;   // 32 x 8

    if (z == 3) {
        // convert x: 128 rows x 32 cols per block
        const int bx = blockIdx.x * 32, by = blockIdx.y * 128;
        #pragma unroll
        for (int j = 0; j < 16; j++) {
            const int row = by + yy + j * 8;
            const int col = bx + xx;
            Xh[(size_t)row * EMB + col] =
                __float2half(x[(size_t)row * EMB + col]);
        }
        return;
    }
    if (z == 2) {
        __shared__ float tbuf[32][33];
        const int bx = blockIdx.x * 32, by = blockIdx.y * 32;
        #pragma unroll
        for (int j = 0; j < 32; j += 8)
            tbuf[yy + j][xx] = Wv[(size_t)(by + yy + j) * EMB + bx + xx];
        __syncthreads();
        #pragma unroll
        for (int j = 0; j < 32; j += 8)
            Wvt[(size_t)(bx + yy + j) * EMB + by + xx] =
                __float2half(tbuf[xx][yy + j]);
        return;
    }
    // z = 0 / 1: elementwise convert of Wq / Wk (32 rows x 32 cols per block)
    const float* in = (z == 0) ? Wq : Wk;
    __half*     out = (z == 0) ? Wqh : Wkh;
    const int bx = blockIdx.x * 32, by = blockIdx.y * 32;
    #pragma unroll
    for (int j = 0; j < 4; j++) {
        const int row = by + yy + j * 8;
        out[(size_t)row * EMB + bx + xx] =
            __float2half(in[(size_t)row * EMB + bx + xx]);
    }
}

// ---------------------------------------------------------------------------
extern "C" void kernel_launch(void* const* d_in, const int* in_sizes, int n_in,
                              void* d_out, int out_size)
{
    const float* x  = (const float*)d_in[0];
    const float* Wq = (const float*)d_in[1];
    const float* Wk = (const float*)d_in[2];
    const float* Wv = (const float*)d_in[3];
    float* out = (float*)d_out;

    __half *Xh, *Wqh, *Wkh, *Wvt, *Mh, *Tt, *Vt, *Sh;
    float *Part;
    cudaGetSymbolAddress((void**)&Xh,  g_Xh);
    cudaGetSymbolAddress((void**)&Wqh, g_Wqh);
    cudaGetSymbolAddress((void**)&Wkh, g_Wkh);
    cudaGetSymbolAddress((void**)&Wvt, g_Wvt);
    cudaGetSymbolAddress((void**)&Mh,  g_M);
    cudaGetSymbolAddress((void**)&Tt,  g_Tt);
    cudaGetSymbolAddress((void**)&Vt,  g_Vt);
    cudaGetSymbolAddress((void**)&Sh,  g_Sh);
    cudaGetSymbolAddress((void**)&Part, g_part);

    cudaFuncSetAttribute(gemm16_k,
        cudaFuncAttributeMaxDynamicSharedMemorySize, GEMM_DYNSMEM);
    cudaFuncSetAttribute(gemmT_k,
        cudaFuncAttributeMaxDynamicSharedMemorySize, GEMM_DYNSMEM);
    cudaFuncSetAttribute(score_k,
        cudaFuncAttributeMaxDynamicSharedMemorySize, GEMM_DYNSMEM);
    cudaFuncSetAttribute(pv_k,
        cudaFuncAttributeMaxDynamicSharedMemorySize, GEMM_DYNSMEM);

    // Side stream + events, created once on the (uncaptured) correctness call.
    static cudaStream_t s2 = nullptr;
    static cudaEvent_t evPrep = nullptr, evT = nullptr;
    if (s2 == nullptr) {
        cudaStreamCreateWithFlags(&s2, cudaStreamNonBlocking);
        cudaEventCreateWithFlags(&evPrep, cudaEventDisableTiming);
        cudaEventCreateWithFlags(&evT,   cudaEventDisableTiming);
    }

    const dim3 blk(128);

    // Prep: Wq/Wk convert, Wv transpose, x convert.
    prep_k<<<dim3(32, 32, 4), dim3(32, 8)>>>(x, Wq, Wk, Wv, Xh, Wqh, Wkh, Wvt);
    cudaEventRecord(evPrep, 0);

    // Side stream: M = Wq @ Wk^T, then Tt = (M @ X^T)^T.
    cudaStreamWaitEvent(s2, evPrep, 0);
    gemm16_k<<<dim3(8, 8), blk, GEMM_DYNSMEM, s2>>>(Wqh, Wkh, Mh, EMB, EMB);
    gemmT_k <<<dim3(32, 8), blk, GEMM_DYNSMEM, s2>>>(Mh, Xh, Tt, SEQ, EMB);
    cudaEventRecord(evT, s2);

    // Main stream (concurrent): Vt = (X @ Wv)^T  via transposed-out proj.
    gemmT_k<<<dim3(8, 32), blk, GEMM_DYNSMEM>>>(Xh, Wvt, Vt, EMB, EMB);

    // Join, then score and PV.
    cudaStreamWaitEvent(0, evT, 0);

    // Scores + fused exp: S = exp((X @ Tt^T)/32)  (== exp(QK^T/32)).
    score_k<<<dim3(32, 32), blk, GEMM_DYNSMEM>>>(Xh, Tt, Sh, Part);

    // Output: out = diag(1/rowsum) * (expS @ Vt^T).
    pv_k<<<dim3(8, 32), blk, GEMM_DYNSMEM>>>(Sh, Vt, out, Part);
}

// round 13
// speedup vs baseline: 1.2206x; 1.0346x over previous
#include <cuda_runtime.h>
#include <cuda_fp16.h>
#include <cstdint>

#define SEQ 4096
#define EMB 1024

// ---------------- scratch (static, allocation-free) ----------------
__device__ __half g_Xh [(size_t)SEQ * EMB];
__device__ __half g_Wqh[(size_t)EMB * EMB];   // fp16(Wq), row-major
__device__ __half g_Wkh[(size_t)EMB * EMB];   // fp16(Wk), row-major
__device__ __half g_Wvt[(size_t)EMB * EMB];   // fp16(Wv^T)
__device__ __half g_M  [(size_t)EMB * EMB];   // Wq @ Wk^T
__device__ __half g_Tt [(size_t)SEQ * EMB];   // (M @ X^T)^T
__device__ __half g_Vt [(size_t)EMB * SEQ];
__device__ __half g_Sh [(size_t)SEQ * SEQ];
__device__ float  g_part[(size_t)SEQ * 64];   // per (row, colCTA*2+wn) partials
__device__ unsigned int g_ready[32];          // per row-block completion count

// ---------------- helpers ----------------
__device__ __forceinline__ uint32_t smem_u32(const void* p) {
    return (uint32_t)__cvta_generic_to_shared(p);
}
__device__ __forceinline__ void cp16(uint32_t s, const void* g) {
    asm volatile("cp.async.cg.shared.global [%0], [%1], 16;" :: "r"(s), "l"(g));
}
__device__ __forceinline__ void cp_commit() {
    asm volatile("cp.async.commit_group;" ::: "memory");
}
template <int N>
__device__ __forceinline__ void cp_wait() {
    asm volatile("cp.async.wait_group %0;" :: "n"(N) : "memory");
}
__device__ __forceinline__ float ex2_mufu(float y) {
    float r;
    asm("ex2.approx.ftz.f32 %0, %1;" : "=f"(r) : "f"(y));
    return r;
}
// exact-split exp2 on the FMA pipe (y = n + f, f in [-.5,.5], degree-5 poly)
__device__ __forceinline__ float ex2_fma(float y) {
    const float MAGIC = 12582912.0f;          // 1.5 * 2^23
    float tm = __fadd_rn(y, MAGIC);
    float f  = __fadd_rn(y, -__fadd_rn(tm, -MAGIC));
    int   eb = (__float_as_int(tm) << 23) + 0x3F800000;
    float pl = 0.0013333558f;
    pl = fmaf(pl, f, 0.0096181291f);
    pl = fmaf(pl, f, 0.0555041087f);
    pl = fmaf(pl, f, 0.2402265069f);
    pl = fmaf(pl, f, 0.6931471806f);
    pl = fmaf(pl, f, 1.0f);
    return __int_as_float(eb) * pl;
}
// m16n8k16 fp16 MMA, fp32 accumulate
__device__ __forceinline__ void mma_f16(
    float& c0, float& c1, float& c2, float& c3,
    uint32_t a0, uint32_t a1, uint32_t a2, uint32_t a3,
    uint32_t b0, uint32_t b1)
{
    asm volatile(
        "mma.sync.aligned.m16n8k16.row.col.f32.f16.f16.f32 "
        "{%0,%1,%2,%3}, {%4,%5,%6,%7}, {%8,%9}, {%0,%1,%2,%3};"
        : "+f"(c0), "+f"(c1), "+f"(c2), "+f"(c3)
        : "r"(a0), "r"(a1), "r"(a2), "r"(a3), "r"(b0), "r"(b1));
}

// ---------------------------------------------------------------------------
// FP16 tensor-core NT GEMM: C[M,N] = f( A[M,K] @ B[N,K]^T )
// 128 threads (4 warps 2x2), warp tile 64x64, CTA tile 128x128, BK=64,
// 3-stage cp.async, one __syncthreads/iter, XOR-swizzled smem,
// scalar-LDS fragment loads (known-good mainloop).
// MODE 0: fp16 out
// MODE 1: Sh = fp16(exp(alpha*acc)); per-(row,warp) partial sums -> part
// MODE 2: fp32 out scaled by rsum computed in prologue from part
// MODE 3: fp16 TRANSPOSED out: C[col*mtot + row]
// ---------------------------------------------------------------------------
#define STG 3
#define OPW (128 * 32)                 // fp16x2 words per operand tile (16KB)
#define STW (2 * OPW)
#define GEMM_DYNSMEM (STG * STW * 4)   // 98304 bytes

template <int MODE>
__device__ __forceinline__ void gemm_body(
    const __half* __restrict__ A, const __half* __restrict__ B,
    void* __restrict__ Cv, int N, int K, float alpha,
    float* __restrict__ part, int bm, int bn, int bx, int mtot)
{
    extern __shared__ uint32_t sm[];
    __shared__ float rsm[128];

    const int tid  = threadIdx.x;
    const int warp = tid >> 5;
    const int lane = tid & 31;
    const int g    = lane >> 2;
    const int t    = lane & 3;
    const int wm   = warp & 1;      // 2 x 64 rows
    const int wn   = warp >> 1;     // 2 x 64 cols

    // MODE 2 prologue: reciprocal row sums for this CTA's 128 rows
    // (fixed-order 64-term sum -> deterministic). Covered by iter-0 barrier.
    if (MODE == 2) {
        const float4* pp = reinterpret_cast<const float4*>(
            part + (size_t)(bm + tid) * 64);
        float s = 0.0f;
        #pragma unroll
        for (int i = 0; i < 16; i++) {
            float4 v = pp[i];
            s += (v.x + v.y) + (v.z + v.w);
        }
        rsm[tid] = 1.0f / s;
    }

    float acc[4][8][4];
    #pragma unroll
    for (int mi = 0; mi < 4; mi++)
        #pragma unroll
        for (int ni = 0; ni < 8; ni++)
            #pragma unroll
            for (int r = 0; r < 4; r++) acc[mi][ni][r] = 0.0f;

    const uint32_t smb = smem_u32(sm);
    const int lrow = tid >> 3;          // 0..15, 8 passes -> 128 rows
    const int lseg = tid & 7;

    auto load_stage = [&](int chunk) {
        const int s  = chunk % STG;
        const int k0 = chunk * 64;
        const uint32_t sa = smb + s * (STW * 4);
        const uint32_t sb = sa + OPW * 4;
        #pragma unroll
        for (int p = 0; p < 8; p++) {
            const int row  = lrow + p * 16;
            const int segS = lseg ^ (row & 7);
            const uint32_t so = (uint32_t)(row * 128 + segS * 16);
            cp16(sa + so, A + (size_t)(bm + row) * K + k0 + lseg * 8);
            cp16(sb + so, B + (size_t)(bn + row) * K + k0 + lseg * 8);
        }
        cp_commit();
    };

    const int NT = K >> 6;

    load_stage(0);
    load_stage(1);

    for (int i = 0; i < NT; i++) {
        const int s = i % STG;
        cp_wait<1>();
        __syncthreads();

        if (i + 2 < NT) load_stage(i + 2);
        else            cp_commit();

        const uint32_t* As  = sm + s * STW;
        const uint32_t* Bsm = As + OPW;
        const int swz = 4 * g;

        #pragma unroll
        for (int ksi = 0; ksi < 4; ksi++) {
            const int c0 = (ksi * 8 + t)     ^ swz;
            const int c2 = (ksi * 8 + t + 4) ^ swz;

            uint32_t af[4][4];
            #pragma unroll
            for (int mi = 0; mi < 4; mi++) {
                const uint32_t* base = As + (wm * 64 + mi * 16 + g) * 32;
                af[mi][0] = base[c0];
                af[mi][1] = base[8 * 32 + c0];
                af[mi][2] = base[c2];
                af[mi][3] = base[8 * 32 + c2];
            }
            uint32_t bf[8][2];
            #pragma unroll
            for (int ni = 0; ni < 8; ni++) {
                const uint32_t* base = Bsm + (wn * 64 + ni * 8 + g) * 32;
                bf[ni][0] = base[c0];
                bf[ni][1] = base[c2];
            }
            #pragma unroll
            for (int mi = 0; mi < 4; mi++)
                #pragma unroll
                for (int ni = 0; ni < 8; ni++)
                    mma_f16(acc[mi][ni][0], acc[mi][ni][1],
                            acc[mi][ni][2], acc[mi][ni][3],
                            af[mi][0], af[mi][1], af[mi][2], af[mi][3],
                            bf[ni][0], bf[ni][1]);
        }
    }

    // ---- epilogue ----
    if (MODE == 0) {
        __half* C = (__half*)Cv;
        #pragma unroll
        for (int mi = 0; mi < 4; mi++) {
            const int row = bm + wm * 64 + mi * 16 + g;
            #pragma unroll
            for (int ni = 0; ni < 8; ni++) {
                const int col = bn + wn * 64 + ni * 8 + 2 * t;
                *reinterpret_cast<__half2*>(&C[(size_t)row * N + col]) =
                    __floats2half2_rn(acc[mi][ni][0], acc[mi][ni][1]);
                *reinterpret_cast<__half2*>(&C[(size_t)(row + 8) * N + col]) =
                    __floats2half2_rn(acc[mi][ni][2], acc[mi][ni][3]);
            }
        }
    } else if (MODE == 1) {
        __half* C = (__half*)Cv;
        const float aL = alpha * 1.4426950408889634f;   // alpha * log2(e)
        #pragma unroll
        for (int mi = 0; mi < 4; mi++) {
            const int row = bm + wm * 64 + mi * 16 + g;
            float sr0 = 0.0f, sr1 = 0.0f;
            #pragma unroll
            for (int ni = 0; ni < 8; ni++) {
                const int col = bn + wn * 64 + ni * 8 + 2 * t;
                float v0, v1, v2, v3;
                if (ni & 1) {                 // FMA pipe
                    v0 = ex2_fma(acc[mi][ni][0] * aL);
                    v1 = ex2_fma(acc[mi][ni][1] * aL);
                    v2 = ex2_fma(acc[mi][ni][2] * aL);
                    v3 = ex2_fma(acc[mi][ni][3] * aL);
                } else {                      // MUFU pipe
                    v0 = ex2_mufu(acc[mi][ni][0] * aL);
                    v1 = ex2_mufu(acc[mi][ni][1] * aL);
                    v2 = ex2_mufu(acc[mi][ni][2] * aL);
                    v3 = ex2_mufu(acc[mi][ni][3] * aL);
                }
                *reinterpret_cast<__half2*>(&C[(size_t)row * N + col]) =
                    __floats2half2_rn(v0, v1);
                *reinterpret_cast<__half2*>(&C[(size_t)(row + 8) * N + col]) =
                    __floats2half2_rn(v2, v3);
                sr0 += v0 + v1;
                sr1 += v2 + v3;
            }
            // sum over the 4 t-lanes (same g)
            sr0 += __shfl_xor_sync(0xFFFFFFFF, sr0, 1);
            sr0 += __shfl_xor_sync(0xFFFFFFFF, sr0, 2);
            sr1 += __shfl_xor_sync(0xFFFFFFFF, sr1, 1);
            sr1 += __shfl_xor_sync(0xFFFFFFFF, sr1, 2);
            if (t == 0) {
                part[(size_t)row * 64 + bx * 2 + wn]       = sr0;
                part[(size_t)(row + 8) * 64 + bx * 2 + wn] = sr1;
            }
        }
    } else if (MODE == 2) {
        float* C = (float*)Cv;
        #pragma unroll
        for (int mi = 0; mi < 4; mi++) {
            const int lr  = wm * 64 + mi * 16 + g;
            const int row = bm + lr;
            const float s0 = rsm[lr];
            const float s1 = rsm[lr + 8];
            #pragma unroll
            for (int ni = 0; ni < 8; ni++) {
                const int col = bn + wn * 64 + ni * 8 + 2 * t;
                *reinterpret_cast<float2*>(&C[(size_t)row * N + col]) =
                    make_float2(acc[mi][ni][0] * s0, acc[mi][ni][1] * s0);
                *reinterpret_cast<float2*>(&C[(size_t)(row + 8) * N + col]) =
                    make_float2(acc[mi][ni][2] * s1, acc[mi][ni][3] * s1);
            }
        }
    } else {
        // MODE 3: transposed fp16 store -> C[col * mtot + row].
        __half* C = (__half*)Cv;
        #pragma unroll
        for (int mi = 0; mi < 4; mi++) {
            const int row = bm + wm * 64 + mi * 16 + g;
            #pragma unroll
            for (int ni = 0; ni < 8; ni++) {
                const int col = bn + wn * 64 + ni * 8 + 2 * t;
                C[(size_t)col * mtot + row]           = __float2half(acc[mi][ni][0]);
                C[(size_t)(col + 1) * mtot + row]     = __float2half(acc[mi][ni][1]);
                C[(size_t)col * mtot + row + 8]       = __float2half(acc[mi][ni][2]);
                C[(size_t)(col + 1) * mtot + row + 8] = __float2half(acc[mi][ni][3]);
            }
        }
    }
}

// Plain fp16-out GEMM (used for M = Wq @ Wk^T).
__global__ void __launch_bounds__(128, 2) gemm16_k(
    const __half* __restrict__ A, const __half* __restrict__ B,
    __half* __restrict__ C, int N, int K)
{
    gemm_body<0>(A, B, C, N, K, 1.0f, nullptr,
                 blockIdx.y * 128, blockIdx.x * 128, blockIdx.x, 0);
}

// Transposed-out GEMM (used for Tt and Vt).
__global__ void __launch_bounds__(128, 2) gemmT_k(
    const __half* __restrict__ A, const __half* __restrict__ B,
    __half* __restrict__ C, int N, int K)
{
    gemm_body<3>(A, B, C, N, K, 1.0f, nullptr,
                 blockIdx.y * 128, blockIdx.x * 128, blockIdx.x,
                 (int)gridDim.y * 128);
}

// ---------------------------------------------------------------------------
// Fused score+PV kernel with row-block readiness counters.
// bid < 1024 : score role — S tile (exp, partial sums), then signal ready[by].
// bid >= 1024: pv role — spin until ready[by]==32, then PV tile.
// 256 pv CTAs < residency slots -> score always has slots -> no deadlock.
// ---------------------------------------------------------------------------
__global__ void __launch_bounds__(128, 2) attn_k(
    const __half* __restrict__ Xh, const __half* __restrict__ Tt,
    __half* __restrict__ Sh, float* __restrict__ part,
    const __half* __restrict__ Vt, float* __restrict__ out,
    unsigned int* __restrict__ ready)
{
    const int bid = blockIdx.x;
    if (bid < 1024) {
        const int bx = bid & 31, by = bid >> 5;
        gemm_body<1>(Xh, Tt, Sh, SEQ, EMB, 0.03125f, part,
                     by * 128, bx * 128, bx, 0);
        __threadfence();                 // each thread's Sh/part stores visible
        __syncthreads();                 // all threads fenced
        if (threadIdx.x == 0) atomicAdd(&ready[by], 1u);
    } else {
        const int pid = bid - 1024;
        const int bx = pid & 7, by = pid >> 3;
        if (threadIdx.x == 0) {
            while (atomicAdd(&ready[by], 0u) < 32u) __nanosleep(200);
            __threadfence();
        }
        __syncthreads();
        gemm_body<2>(Sh, Vt, out, EMB, SEQ, 1.0f, part,
                     by * 128, bx * 128, bx, 0);
    }
}

// ---------------------------------------------------------------------------
// Fused prep: z=0 convert Wq; z=1 convert Wk; z=2 transpose Wv; z=3 convert x.
// grid (32, 32, 4), block (32, 8).
// ---------------------------------------------------------------------------
__global__ void __launch_bounds__(256) prep_k(
    const float* __restrict__ x,
    const float* __restrict__ Wq, const float* __restrict__ Wk,
    const float* __restrict__ Wv,
    __half* __restrict__ Xh,
    __half* __restrict__ Wqh, __half* __restrict__ Wkh,
    __half* __restrict__ Wvt)
{
    const int z = blockIdx.z;
    const int xx = threadIdx.x, yy = threadIdx.y;   // 32 x 8

    if (z == 3) {
        const int bx = blockIdx.x * 32, by = blockIdx.y * 128;
        #pragma unroll
        for (int j = 0; j < 16; j++) {
            const int row = by + yy + j * 8;
            const int col = bx + xx;
            Xh[(size_t)row * EMB + col] =
                __float2half(x[(size_t)row * EMB + col]);
        }
        return;
    }
    if (z == 2) {
        __shared__ float tbuf[32][33];
        const int bx = blockIdx.x * 32, by = blockIdx.y * 32;
        #pragma unroll
        for (int j = 0; j < 32; j += 8)
            tbuf[yy + j][xx] = Wv[(size_t)(by + yy + j) * EMB + bx + xx];
        __syncthreads();
        #pragma unroll
        for (int j = 0; j < 32; j += 8)
            Wvt[(size_t)(bx + yy + j) * EMB + by + xx] =
                __float2half(tbuf[xx][yy + j]);
        return;
    }
    const float* in = (z == 0) ? Wq : Wk;
    __half*     out = (z == 0) ? Wqh : Wkh;
    const int bx = blockIdx.x * 32, by = blockIdx.y * 32;
    #pragma unroll
    for (int j = 0; j < 4; j++) {
        const int row = by + yy + j * 8;
        out[(size_t)row * EMB + bx + xx] =
            __float2half(in[(size_t)row * EMB + bx + xx]);
    }
}

// ---------------------------------------------------------------------------
extern "C" void kernel_launch(void* const* d_in, const int* in_sizes, int n_in,
                              void* d_out, int out_size)
{
    const float* x  = (const float*)d_in[0];
    const float* Wq = (const float*)d_in[1];
    const float* Wk = (const float*)d_in[2];
    const float* Wv = (const float*)d_in[3];
    float* out = (float*)d_out;

    __half *Xh, *Wqh, *Wkh, *Wvt, *Mh, *Tt, *Vt, *Sh;
    float *Part;
    unsigned int* Ready;
    cudaGetSymbolAddress((void**)&Xh,  g_Xh);
    cudaGetSymbolAddress((void**)&Wqh, g_Wqh);
    cudaGetSymbolAddress((void**)&Wkh, g_Wkh);
    cudaGetSymbolAddress((void**)&Wvt, g_Wvt);
    cudaGetSymbolAddress((void**)&Mh,  g_M);
    cudaGetSymbolAddress((void**)&Tt,  g_Tt);
    cudaGetSymbolAddress((void**)&Vt,  g_Vt);
    cudaGetSymbolAddress((void**)&Sh,  g_Sh);
    cudaGetSymbolAddress((void**)&Part, g_part);
    cudaGetSymbolAddress((void**)&Ready, g_ready);

    cudaFuncSetAttribute(gemm16_k,
        cudaFuncAttributeMaxDynamicSharedMemorySize, GEMM_DYNSMEM);
    cudaFuncSetAttribute(gemmT_k,
        cudaFuncAttributeMaxDynamicSharedMemorySize, GEMM_DYNSMEM);
    cudaFuncSetAttribute(attn_k,
        cudaFuncAttributeMaxDynamicSharedMemorySize, GEMM_DYNSMEM);

    // Side stream + events, created once on the (uncaptured) correctness call.
    static cudaStream_t s2 = nullptr;
    static cudaEvent_t evPrep = nullptr, evT = nullptr;
    if (s2 == nullptr) {
        cudaStreamCreateWithFlags(&s2, cudaStreamNonBlocking);
        cudaEventCreateWithFlags(&evPrep, cudaEventDisableTiming);
        cudaEventCreateWithFlags(&evT,   cudaEventDisableTiming);
    }

    const dim3 blk(128);

    // Reset readiness counters (graph-capturable async memset).
    cudaMemsetAsync(Ready, 0, 32 * sizeof(unsigned int), 0);

    // Prep: Wq/Wk convert, Wv transpose, x convert.
    prep_k<<<dim3(32, 32, 4), dim3(32, 8)>>>(x, Wq, Wk, Wv, Xh, Wqh, Wkh, Wvt);
    cudaEventRecord(evPrep, 0);

    // Side stream: M = Wq @ Wk^T, then Tt = (M @ X^T)^T.
    cudaStreamWaitEvent(s2, evPrep, 0);
    gemm16_k<<<dim3(8, 8), blk, GEMM_DYNSMEM, s2>>>(Wqh, Wkh, Mh, EMB, EMB);
    gemmT_k <<<dim3(32, 8), blk, GEMM_DYNSMEM, s2>>>(Mh, Xh, Tt, SEQ, EMB);
    cudaEventRecord(evT, s2);

    // Main stream (concurrent): Vt = (X @ Wv)^T  via transposed-out proj.
    gemmT_k<<<dim3(8, 32), blk, GEMM_DYNSMEM>>>(Xh, Wvt, Vt, EMB, EMB);

    // Join, then the fused score+PV kernel.
    cudaStreamWaitEvent(0, evT, 0);
    attn_k<<<dim3(1280), blk, GEMM_DYNSMEM>>>(Xh, Tt, Sh, Part, Vt, out, Ready);
}